// round 12
// baseline (speedup 1.0000x reference)
#include <cuda_runtime.h>
#include <cuda_bf16.h>
#include <cmath>
#include <cstdint>

#define N_TOK 4096
#define E_DIM 512
#define NH 8
#define DK 64
#define WSZ 128
#define NBLK 32
#define NDIMS 16
#define QKV_LD 1536
#define CHUNKS 64
#define CLEN 64
#define KDIM 512

// ---------------- scratch (device globals) ----------------
__device__ float g_qkv [N_TOK * QKV_LD];
__device__ float g_cema[N_TOK * E_DIM];
__device__ float g_hend [CHUNKS * E_DIM * NDIMS];
__device__ float g_carry[CHUNKS * E_DIM * NDIMS];
__device__ float g_sv[E_DIM];
__device__ float g_xsum[E_DIM];
__device__ __nv_bfloat16 g_xhi [N_TOK * E_DIM];
__device__ __nv_bfloat16 g_xlo [N_TOK * E_DIM];
__device__ __nv_bfloat16 g_ahi [N_TOK * E_DIM];
__device__ __nv_bfloat16 g_alo [N_TOK * E_DIM];
__device__ __nv_bfloat16 g_wqT_hi[QKV_LD * E_DIM];
__device__ __nv_bfloat16 g_wqT_lo[QKV_LD * E_DIM];
__device__ __nv_bfloat16 g_woT_hi[E_DIM * E_DIM];
__device__ __nv_bfloat16 g_woT_lo[E_DIM * E_DIM];

// ---------------- PTX helpers ----------------
__device__ __forceinline__ uint32_t smem_u32(const void* p) {
    uint32_t a;
    asm("{ .reg .u64 t; cvta.to.shared.u64 t, %1; cvt.u32.u64 %0, t; }" : "=r"(a) : "l"(p));
    return a;
}
__device__ __forceinline__ void ldsm_x4(uint32_t* r, uint32_t addr) {
    asm volatile("ldmatrix.sync.aligned.m8n8.x4.shared.b16 {%0,%1,%2,%3}, [%4];"
        : "=r"(r[0]), "=r"(r[1]), "=r"(r[2]), "=r"(r[3]) : "r"(addr));
}
__device__ __forceinline__ void ldsm_x2(uint32_t* r, uint32_t addr) {
    asm volatile("ldmatrix.sync.aligned.m8n8.x2.shared.b16 {%0,%1}, [%2];"
        : "=r"(r[0]), "=r"(r[1]) : "r"(addr));
}
__device__ __forceinline__ void mma_bf16(float* d, const uint32_t* a, const uint32_t* b) {
    asm volatile("mma.sync.aligned.m16n8k16.row.col.f32.bf16.bf16.f32 "
        "{%0,%1,%2,%3}, {%4,%5,%6,%7}, {%8,%9}, {%0,%1,%2,%3};"
        : "+f"(d[0]), "+f"(d[1]), "+f"(d[2]), "+f"(d[3])
        : "r"(a[0]), "r"(a[1]), "r"(a[2]), "r"(a[3]), "r"(b[0]), "r"(b[1]));
}
#define CP_ASYNC16(dst, src) \
    asm volatile("cp.async.cg.shared.global [%0], [%1], 16;" :: "r"(dst), "l"(src))
#define CP_COMMIT()  asm volatile("cp.async.commit_group;" ::: "memory")
#define CP_WAIT_1()  asm volatile("cp.async.wait_group 1;" ::: "memory")
#define CP_WAIT_0()  asm volatile("cp.async.wait_group 0;" ::: "memory")

// ---------------- prep kernels ----------------
__global__ void conv_hilo(const float* __restrict__ X,
                          __nv_bfloat16* __restrict__ hi, __nv_bfloat16* __restrict__ lo)
{
    const int i = blockIdx.x * blockDim.x + threadIdx.x;   // per float4
    float4 v = ((const float4*)X)[i];
    __nv_bfloat16 hx = __float2bfloat16(v.x), hy = __float2bfloat16(v.y);
    __nv_bfloat16 hz = __float2bfloat16(v.z), hw = __float2bfloat16(v.w);
    __nv_bfloat162* H = (__nv_bfloat162*)hi;
    __nv_bfloat162* L = (__nv_bfloat162*)lo;
    H[i * 2 + 0] = __nv_bfloat162{hx, hy};
    H[i * 2 + 1] = __nv_bfloat162{hz, hw};
    L[i * 2 + 0] = __nv_bfloat162{__float2bfloat16(v.x - __bfloat162float(hx)),
                                  __float2bfloat16(v.y - __bfloat162float(hy))};
    L[i * 2 + 1] = __nv_bfloat162{__float2bfloat16(v.z - __bfloat162float(hz)),
                                  __float2bfloat16(v.w - __bfloat162float(hw))};
}

// W [Kdim x Ndim] fp32 -> WT [Ndim x Kdim] bf16 hi/lo
__global__ void transpose_conv(const float* __restrict__ W,
                               __nv_bfloat16* __restrict__ Thi, __nv_bfloat16* __restrict__ Tlo,
                               int Kdim, int Ndim)
{
    __shared__ float t[32][33];
    const int n0 = blockIdx.x * 32, k0 = blockIdx.y * 32;
    const int tx = threadIdx.x, ty = threadIdx.y;
#pragma unroll
    for (int s = 0; s < 32; s += 8)
        t[ty + s][tx] = W[(k0 + ty + s) * Ndim + n0 + tx];
    __syncthreads();
#pragma unroll
    for (int s = 0; s < 32; s += 8) {
        float v = t[tx][ty + s];
        __nv_bfloat16 h = __float2bfloat16(v);
        Thi[(n0 + ty + s) * Kdim + k0 + tx] = h;
        Tlo[(n0 + ty + s) * Kdim + k0 + tx] = __float2bfloat16(v - __bfloat162float(h));
    }
}

// ---------------- S_v = (sum_t x_t) @ W_v + 4096*b_v ----------------
__global__ void xsum_kernel(const float* __restrict__ x)
{
    const int c  = threadIdx.x;
    const int t0 = blockIdx.x * 128;
    float s = 0.f;
#pragma unroll 4
    for (int t = t0; t < t0 + 128; t++)
        s += x[t * E_DIM + c];
    atomicAdd(&g_xsum[c], s);
}

__global__ void sv_gemv(const float* __restrict__ W_qkv, const float* __restrict__ b_qkv)
{
    __shared__ float xs[E_DIM];
    const int c = threadIdx.x;
    xs[c] = g_xsum[c];
    __syncthreads();
    float s = 4096.f * b_qkv[2 * E_DIM + c];
    for (int e = 0; e < E_DIM; e++)
        s = fmaf(xs[e], W_qkv[e * QKV_LD + 2 * E_DIM + c], s);
    g_sv[c] = s;
}

// ---------------- bf16x3 tensor-core GEMM ----------------
#define KC 32
#define NCH (KDIM / KC)
#define LDSB 80
#define ST_AH 0
#define ST_AL 5120
#define ST_BH 10240
#define ST_BL 20480
#define STAGE_B 30720
#define GEMM_SMEM_BYTES (2 * STAGE_B)

__device__ __forceinline__ void gemm_load_chunk(
    uint32_t stage_sb, const __nv_bfloat16* Ahi, const __nv_bfloat16* Alo,
    const __nv_bfloat16* Bhi, const __nv_bfloat16* Blo,
    int m0, int n0, int kb, int tid)
{
#pragma unroll
    for (int i = 0; i < 2; i++) {
        const int idx = tid + i * 128;
        const int r = idx >> 2, seg = idx & 3;
        const uint32_t so = stage_sb + (uint32_t)(r * LDSB + seg * 16);
        const long ga = (long)(m0 + r) * KDIM + kb + seg * 8;
        CP_ASYNC16(so + ST_AH, Ahi + ga);
        CP_ASYNC16(so + ST_AL, Alo + ga);
    }
#pragma unroll
    for (int i = 0; i < 4; i++) {
        const int idx = tid + i * 128;
        const int r = idx >> 2, seg = idx & 3;
        const uint32_t so = stage_sb + (uint32_t)(r * LDSB + seg * 16);
        const long gb = (long)(n0 + r) * KDIM + kb + seg * 8;
        CP_ASYNC16(so + ST_BH, Bhi + gb);
        CP_ASYNC16(so + ST_BL, Blo + gb);
    }
}

__global__ void __launch_bounds__(128, 3)
gemm_mma(const __nv_bfloat16* __restrict__ Ahi, const __nv_bfloat16* __restrict__ Alo,
         const __nv_bfloat16* __restrict__ Bhi, const __nv_bfloat16* __restrict__ Blo,
         const float* __restrict__ bias, float* __restrict__ C, int ldc, int mode,
         int m_base,
         const float* __restrict__ cema, const float* __restrict__ aw)
{
    extern __shared__ __align__(16) char smem[];
    const uint32_t sb = smem_u32(smem);
    const int tid = threadIdx.x;
    const int wn = tid >> 5, lane = tid & 31;
    const int m0 = m_base + blockIdx.y * 64, n0 = blockIdx.x * 128;

    const uint32_t a_off = (uint32_t)(lane & 15) * LDSB + ((lane >> 4) << 4);
    const uint32_t b_off = (uint32_t)(wn * 32 + (lane & 7)) * LDSB + (((lane >> 3) & 1) << 4);

    float acc[4][4][4];
#pragma unroll
    for (int mt = 0; mt < 4; mt++)
#pragma unroll
        for (int nt = 0; nt < 4; nt++)
#pragma unroll
            for (int c = 0; c < 4; c++) acc[mt][nt][c] = 0.f;

    gemm_load_chunk(sb, Ahi, Alo, Bhi, Blo, m0, n0, 0, tid);
    CP_COMMIT();

    for (int ch = 0; ch < NCH; ch++) {
        const uint32_t st = sb + (uint32_t)((ch & 1) * STAGE_B);
        if (ch + 1 < NCH) {
            gemm_load_chunk(sb + (uint32_t)(((ch + 1) & 1) * STAGE_B),
                            Ahi, Alo, Bhi, Blo, m0, n0, (ch + 1) * KC, tid);
            CP_COMMIT();
            CP_WAIT_1();
        } else {
            CP_WAIT_0();
        }
        __syncthreads();

#pragma unroll
        for (int ks = 0; ks < 2; ks++) {
            const uint32_t kofs = ks * 32;
            uint32_t bh[4][2], bl[4][2];
#pragma unroll
            for (int nt = 0; nt < 4; nt++) {
                ldsm_x2(bh[nt], st + ST_BH + b_off + nt * (8 * LDSB) + kofs);
                ldsm_x2(bl[nt], st + ST_BL + b_off + nt * (8 * LDSB) + kofs);
            }
#pragma unroll
            for (int mt = 0; mt < 4; mt++) {
                uint32_t ah[4], al[4];
                ldsm_x4(ah, st + ST_AH + a_off + mt * (16 * LDSB) + kofs);
                ldsm_x4(al, st + ST_AL + a_off + mt * (16 * LDSB) + kofs);
#pragma unroll
                for (int nt = 0; nt < 4; nt++) {
                    mma_bf16(acc[mt][nt], ah, bh[nt]);
                    mma_bf16(acc[mt][nt], ah, bl[nt]);
                    mma_bf16(acc[mt][nt], al, bh[nt]);
                }
            }
        }
        __syncthreads();
    }

    float w0 = 1.f, w1 = 0.f;
    if (mode == 1) {
        float a0 = aw[0], a1 = aw[1];
        float mx = fmaxf(a0, a1);
        float e0 = expf(a0 - mx), e1 = expf(a1 - mx);
        float inv = 1.f / (e0 + e1);
        w0 = e0 * inv; w1 = e1 * inv;
    }

#pragma unroll
    for (int mt = 0; mt < 4; mt++) {
        const int r0 = m0 + mt * 16 + (lane >> 2);
#pragma unroll
        for (int nt = 0; nt < 4; nt++) {
            const int col = n0 + wn * 32 + nt * 8 + (lane & 3) * 2;
            const float b0v = bias[col], b1v = bias[col + 1];
            float2 v0 = make_float2(acc[mt][nt][0] + b0v, acc[mt][nt][1] + b1v);
            float2 v1 = make_float2(acc[mt][nt][2] + b0v, acc[mt][nt][3] + b1v);
            if (mode == 1) {
                float2 c0 = *(const float2*)&cema[r0 * ldc + col];
                float2 c1 = *(const float2*)&cema[(r0 + 8) * ldc + col];
                v0.x = fmaf(w0, v0.x, w1 * c0.x);  v0.y = fmaf(w0, v0.y, w1 * c0.y);
                v1.x = fmaf(w0, v1.x, w1 * c1.x);  v1.y = fmaf(w0, v1.y, w1 * c1.y);
            }
            *(float2*)&C[r0 * ldc + col]       = v0;
            *(float2*)&C[(r0 + 8) * ldc + col] = v1;
        }
    }
}

// ---------------- fused block-local attention (half-range) ----------------
#define ATTN_SMEM_FLOATS (16384 + 8192 + 128)

__global__ void __launch_bounds__(256)
attn_kernel(int blk_base)
{
    extern __shared__ float sm[];
    float* qv     = sm;
    float* ks     = sm + 8192;
    float* Est    = sm;
    float* vv     = sm + 16384;
    float* rowinv = sm + 16384 + 8192;

    const int tid = threadIdx.x;
    const int h   = blockIdx.x >> 4;            // grid = NH * 16
    const int blk = blk_base + (blockIdx.x & 15);
    const int t0  = blk * WSZ;
    const int coff = h * DK;

    for (int idx = tid; idx < 2048; idx += 256) {
        const int i = idx >> 4, d4 = (idx & 15) << 2;
        const float* src = &g_qkv[(t0 + i) * QKV_LD + coff + d4];
        float4 q4 = *(const float4*)src;
        float4 k4 = *(const float4*)(src + E_DIM);
        float4 v4 = *(const float4*)(src + 2 * E_DIM);
        qv[(d4 + 0) * 128 + i] = q4.x;  ks[(d4 + 0) * 128 + i] = k4.x;
        qv[(d4 + 1) * 128 + i] = q4.y;  ks[(d4 + 1) * 128 + i] = k4.y;
        qv[(d4 + 2) * 128 + i] = q4.z;  ks[(d4 + 2) * 128 + i] = k4.z;
        qv[(d4 + 3) * 128 + i] = q4.w;  ks[(d4 + 3) * 128 + i] = k4.w;
        *(float4*)&vv[i * 64 + d4] = v4;
    }
    __syncthreads();

    const int tx = tid & 15, ty = tid >> 4;
    const int ib = tx * 8, jb = ty * 8;
    float accS[8][8];
#pragma unroll
    for (int r = 0; r < 8; r++)
#pragma unroll
        for (int c = 0; c < 8; c++) accS[r][c] = 0.f;

#pragma unroll 4
    for (int d = 0; d < 64; d++) {
        float qr[8], kr[8];
        *(float4*)&qr[0] = *(const float4*)&qv[d * 128 + ib];
        *(float4*)&qr[4] = *(const float4*)&qv[d * 128 + ib + 4];
        *(float4*)&kr[0] = *(const float4*)&ks[d * 128 + jb];
        *(float4*)&kr[4] = *(const float4*)&ks[d * 128 + jb + 4];
#pragma unroll
        for (int r = 0; r < 8; r++)
#pragma unroll
            for (int c = 0; c < 8; c++)
                accS[r][c] = fmaf(qr[r], kr[c], accS[r][c]);
    }
    __syncthreads();

#pragma unroll
    for (int c = 0; c < 8; c++) {
        const int j = jb + c;
        float e[8];
#pragma unroll
        for (int r = 0; r < 8; r++) {
            const int i = ib + r;
            e[r] = (j <= i) ? (expf(accS[r][c] * 0.125f) - 1.0f) : 0.0f;
        }
        *(float4*)&Est[j * 128 + ib]     = make_float4(e[0], e[1], e[2], e[3]);
        *(float4*)&Est[j * 128 + ib + 4] = make_float4(e[4], e[5], e[6], e[7]);
    }
    __syncthreads();

    if (tid < 128) {
        float s = 0.f;
#pragma unroll 4
        for (int j = 0; j < 128; j++) s += Est[j * 128 + tid];
        rowinv[tid] = 1.0f / (s + 4096.0f);
    }
    __syncthreads();

    const int i0 = ty * 8, d0 = tx * 4;
    float accO[8][4];
#pragma unroll
    for (int r = 0; r < 8; r++)
#pragma unroll
        for (int c = 0; c < 4; c++) accO[r][c] = 0.f;

#pragma unroll 2
    for (int j = 0; j < 128; j++) {
        float er[8];
        *(float4*)&er[0] = *(const float4*)&Est[j * 128 + i0];
        *(float4*)&er[4] = *(const float4*)&Est[j * 128 + i0 + 4];
        float4 v4 = *(const float4*)&vv[j * 64 + d0];
#pragma unroll
        for (int r = 0; r < 8; r++) {
            accO[r][0] = fmaf(er[r], v4.x, accO[r][0]);
            accO[r][1] = fmaf(er[r], v4.y, accO[r][1]);
            accO[r][2] = fmaf(er[r], v4.z, accO[r][2]);
            accO[r][3] = fmaf(er[r], v4.w, accO[r][3]);
        }
    }

    const float4 sv4 = *(const float4*)&g_sv[coff + d0];
#pragma unroll
    for (int r = 0; r < 8; r++) {
        const int i = i0 + r;
        const float riv = rowinv[i];
        float4 o;
        o.x = (accO[r][0] + sv4.x) * riv;
        o.y = (accO[r][1] + sv4.y) * riv;
        o.z = (accO[r][2] + sv4.z) * riv;
        o.w = (accO[r][3] + sv4.w) * riv;
        __nv_bfloat16 hx = __float2bfloat16(o.x), hy = __float2bfloat16(o.y);
        __nv_bfloat16 hz = __float2bfloat16(o.z), hw = __float2bfloat16(o.w);
        const int base = ((t0 + i) * E_DIM + coff + d0) >> 1;
        __nv_bfloat162* H = (__nv_bfloat162*)g_ahi;
        __nv_bfloat162* L = (__nv_bfloat162*)g_alo;
        H[base + 0] = __nv_bfloat162{hx, hy};
        H[base + 1] = __nv_bfloat162{hz, hw};
        L[base + 0] = __nv_bfloat162{__float2bfloat16(o.x - __bfloat162float(hx)),
                                     __float2bfloat16(o.y - __bfloat162float(hy))};
        L[base + 1] = __nv_bfloat162{__float2bfloat16(o.z - __bfloat162float(hz)),
                                     __float2bfloat16(o.w - __bfloat162float(hw))};
    }
}

// ---------------- CEMA: chunked linear scan ----------------
__global__ void __launch_bounds__(128)
cema_pass1(const float* __restrict__ x, const float* __restrict__ p_coeff,
           const float* __restrict__ q_coeff, const float* __restrict__ gamma)
{
    const int gid  = blockIdx.x * 128 + threadIdx.x;
    const int e    = gid & 511;
    const int chnk = gid >> 9;
    float p[NDIMS], q[NDIMS], g[NDIMS], h[NDIMS];
#pragma unroll
    for (int d = 0; d < NDIMS; d++) {
        p[d] = p_coeff[e * NDIMS + d];
        q[d] = q_coeff[e * NDIMS + d];
        g[d] = gamma  [e * NDIMS + d];
        h[d] = 0.f;
    }
    const int tbase = chnk * CLEN;
    for (int t = 0; t < CLEN; t++) {
        const float xv = x[(tbase + t) * E_DIM + e];
        float y = 0.f;
#pragma unroll
        for (int d = 0; d < NDIMS; d++) {
            h[d] = fmaf(q[d], h[d], p[d] * xv);
            y    = fmaf(g[d], h[d], y);
        }
        g_cema[(tbase + t) * E_DIM + e] = y;
    }
#pragma unroll
    for (int d = 0; d < NDIMS; d++)
        g_hend[chnk * (E_DIM * NDIMS) + e * NDIMS + d] = h[d];
}

// latency-hidden carry scan: batch-prefetch 16 hend values, register-only chain
__global__ void __launch_bounds__(128)
cema_carry(const float* __restrict__ q_coeff)
{
    const int gid = blockIdx.x * 128 + threadIdx.x;    // e*16+d
    const float q = q_coeff[gid];
    float qc = q;
#pragma unroll
    for (int i = 0; i < 6; i++) qc *= qc;              // q^64
    float G = 0.f;
    for (int cb = 0; cb < CHUNKS; cb += 16) {
        float v[16];
#pragma unroll
        for (int i = 0; i < 16; i++)
            v[i] = g_hend[(cb + i) * (E_DIM * NDIMS) + gid];
#pragma unroll
        for (int i = 0; i < 16; i++) {
            g_carry[(cb + i) * (E_DIM * NDIMS) + gid] = G;
            G = fmaf(qc, G, v[i]);
        }
    }
}

__global__ void __launch_bounds__(128)
cema_pass2(const float* __restrict__ q_coeff, const float* __restrict__ gamma)
{
    const int gid  = blockIdx.x * 128 + threadIdx.x;
    const int e    = gid & 511;
    const int chnk = gid >> 9;
    if (chnk == 0) return;
    float q[NDIMS], w[NDIMS];
#pragma unroll
    for (int d = 0; d < NDIMS; d++) {
        q[d] = q_coeff[e * NDIMS + d];
        w[d] = gamma[e * NDIMS + d] * g_carry[chnk * (E_DIM * NDIMS) + e * NDIMS + d];
    }
    const int tbase = chnk * CLEN;
    for (int t = 0; t < CLEN; t++) {
        float y = 0.f;
#pragma unroll
        for (int d = 0; d < NDIMS; d++) {
            w[d] *= q[d];
            y    += w[d];
        }
        g_cema[(tbase + t) * E_DIM + e] += y;
    }
}

// ---------------------------- launch ----------------------------
extern "C" void kernel_launch(void* const* d_in, const int* in_sizes, int n_in,
                              void* d_out, int out_size)
{
    (void)in_sizes; (void)n_in; (void)out_size;
    const float* x       = (const float*)d_in[0];
    const float* W_qkv   = (const float*)d_in[1];
    const float* b_qkv   = (const float*)d_in[2];
    const float* W_out   = (const float*)d_in[3];
    const float* b_out   = (const float*)d_in[4];
    const float* p_coeff = (const float*)d_in[6];
    const float* q_coeff = (const float*)d_in[7];
    const float* gamma   = (const float*)d_in[8];
    const float* aw      = (const float*)d_in[9];
    float* out = (float*)d_out;

    float *qkvp, *cemap, *xsump;
    __nv_bfloat16 *xhi, *xlo, *ahi, *alo, *wqh, *wql, *woh, *wol;
    cudaGetSymbolAddress((void**)&qkvp,  g_qkv);
    cudaGetSymbolAddress((void**)&cemap, g_cema);
    cudaGetSymbolAddress((void**)&xsump, g_xsum);
    cudaGetSymbolAddress((void**)&xhi, g_xhi);
    cudaGetSymbolAddress((void**)&xlo, g_xlo);
    cudaGetSymbolAddress((void**)&ahi, g_ahi);
    cudaGetSymbolAddress((void**)&alo, g_alo);
    cudaGetSymbolAddress((void**)&wqh, g_wqT_hi);
    cudaGetSymbolAddress((void**)&wql, g_wqT_lo);
    cudaGetSymbolAddress((void**)&woh, g_woT_hi);
    cudaGetSymbolAddress((void**)&wol, g_woT_lo);

    cudaFuncSetAttribute(gemm_mma, cudaFuncAttributeMaxDynamicSharedMemorySize, GEMM_SMEM_BYTES);
    cudaFuncSetAttribute(attn_kernel, cudaFuncAttributeMaxDynamicSharedMemorySize,
                         ATTN_SMEM_FLOATS * (int)sizeof(float));

    // one-time host-object setup (host-side objects only)
    static cudaStream_t s_side = nullptr, s_attn = nullptr;
    static cudaEvent_t  e_fork = nullptr, e_sv = nullptr, e_g1a = nullptr,
                        e_attnA = nullptr, e_side = nullptr;
    if (s_side == nullptr) {
        cudaStreamCreateWithFlags(&s_side, cudaStreamNonBlocking);
        cudaStreamCreateWithFlags(&s_attn, cudaStreamNonBlocking);
        cudaEventCreateWithFlags(&e_fork,  cudaEventDisableTiming);
        cudaEventCreateWithFlags(&e_sv,    cudaEventDisableTiming);
        cudaEventCreateWithFlags(&e_g1a,   cudaEventDisableTiming);
        cudaEventCreateWithFlags(&e_attnA, cudaEventDisableTiming);
        cudaEventCreateWithFlags(&e_side,  cudaEventDisableTiming);
    }

    // ---- fork side stream: S_v (xsum + gemv), CEMA chain, W_out transpose
    cudaEventRecord(e_fork, 0);
    cudaStreamWaitEvent(s_side, e_fork, 0);

    cudaMemsetAsync(xsump, 0, E_DIM * sizeof(float), s_side);
    xsum_kernel<<<NBLK, E_DIM, 0, s_side>>>(x);
    sv_gemv<<<1, E_DIM, 0, s_side>>>(W_qkv, b_qkv);
    cudaEventRecord(e_sv, s_side);

    cema_pass1<<<(E_DIM * CHUNKS) / 128, 128, 0, s_side>>>(x, p_coeff, q_coeff, gamma);
    cema_carry<<<(E_DIM * NDIMS) / 128, 128, 0, s_side>>>(q_coeff);
    cema_pass2<<<(E_DIM * CHUNKS) / 128, 128, 0, s_side>>>(q_coeff, gamma);
    transpose_conv<<<dim3(E_DIM / 32, E_DIM / 32), dim3(32, 8), 0, s_side>>>(
        W_out, woh, wol, E_DIM, E_DIM);
    cudaEventRecord(e_side, s_side);

    // ---- main: prep -> gemm1 half A -> gemm1 half B
    conv_hilo<<<(N_TOK * E_DIM / 4) / 256, 256>>>(x, xhi, xlo);
    transpose_conv<<<dim3(QKV_LD / 32, E_DIM / 32), dim3(32, 8)>>>(W_qkv, wqh, wql, E_DIM, QKV_LD);

    gemm_mma<<<dim3(QKV_LD / 128, (N_TOK / 2) / 64), 128, GEMM_SMEM_BYTES>>>(
        xhi, xlo, wqh, wql, b_qkv, qkvp, QKV_LD, 0, 0, nullptr, nullptr);
    cudaEventRecord(e_g1a, 0);

    gemm_mma<<<dim3(QKV_LD / 128, (N_TOK / 2) / 64), 128, GEMM_SMEM_BYTES>>>(
        xhi, xlo, wqh, wql, b_qkv, qkvp, QKV_LD, 0, N_TOK / 2, nullptr, nullptr);

    // ---- attn half A on s_attn, concurrent with gemm1 half B
    cudaStreamWaitEvent(s_attn, e_g1a, 0);
    cudaStreamWaitEvent(s_attn, e_sv, 0);
    attn_kernel<<<NH * 16, 256, ATTN_SMEM_FLOATS * (int)sizeof(float), s_attn>>>(0);
    cudaEventRecord(e_attnA, s_attn);

    // ---- attn half B on main (after gemm1b; needs S_v too)
    cudaStreamWaitEvent(0, e_sv, 0);
    attn_kernel<<<NH * 16, 256, ATTN_SMEM_FLOATS * (int)sizeof(float)>>>(16);

    // ---- join everything, then fused output GEMM
    cudaStreamWaitEvent(0, e_attnA, 0);
    cudaStreamWaitEvent(0, e_side, 0);
    gemm_mma<<<dim3(E_DIM / 128, N_TOK / 64), 128, GEMM_SMEM_BYTES>>>(
        ahi, alo, woh, wol, b_out, out, E_DIM, 1, 0, cemap, aw);
}

// round 14
// speedup vs baseline: 1.0655x; 1.0655x over previous
#include <cuda_runtime.h>
#include <cuda_bf16.h>
#include <cmath>
#include <cstdint>

#define N_TOK 4096
#define E_DIM 512
#define NH 8
#define DK 64
#define WSZ 128
#define NBLK 32
#define NDIMS 16
#define QKV_LD 1536
#define CHUNKS 64
#define CLEN 64
#define KDIM 512

// ---------------- scratch (device globals) ----------------
__device__ float g_qkv [N_TOK * QKV_LD];
__device__ float g_cema[N_TOK * E_DIM];
__device__ float g_hend [CHUNKS * E_DIM * NDIMS];
__device__ float g_carry[CHUNKS * E_DIM * NDIMS];
__device__ float g_sv[E_DIM];
__device__ float g_xsum[E_DIM];
__device__ __nv_bfloat16 g_xhi [N_TOK * E_DIM];
__device__ __nv_bfloat16 g_xlo [N_TOK * E_DIM];
__device__ __nv_bfloat16 g_ahi [N_TOK * E_DIM];
__device__ __nv_bfloat16 g_alo [N_TOK * E_DIM];
__device__ __nv_bfloat16 g_wqT_hi[QKV_LD * E_DIM];
__device__ __nv_bfloat16 g_wqT_lo[QKV_LD * E_DIM];
__device__ __nv_bfloat16 g_woT_hi[E_DIM * E_DIM];
__device__ __nv_bfloat16 g_woT_lo[E_DIM * E_DIM];

// ---------------- PTX helpers ----------------
__device__ __forceinline__ uint32_t smem_u32(const void* p) {
    uint32_t a;
    asm("{ .reg .u64 t; cvta.to.shared.u64 t, %1; cvt.u32.u64 %0, t; }" : "=r"(a) : "l"(p));
    return a;
}
__device__ __forceinline__ void ldsm_x4(uint32_t* r, uint32_t addr) {
    asm volatile("ldmatrix.sync.aligned.m8n8.x4.shared.b16 {%0,%1,%2,%3}, [%4];"
        : "=r"(r[0]), "=r"(r[1]), "=r"(r[2]), "=r"(r[3]) : "r"(addr));
}
__device__ __forceinline__ void ldsm_x2(uint32_t* r, uint32_t addr) {
    asm volatile("ldmatrix.sync.aligned.m8n8.x2.shared.b16 {%0,%1}, [%2];"
        : "=r"(r[0]), "=r"(r[1]) : "r"(addr));
}
__device__ __forceinline__ void mma_bf16(float* d, const uint32_t* a, const uint32_t* b) {
    asm volatile("mma.sync.aligned.m16n8k16.row.col.f32.bf16.bf16.f32 "
        "{%0,%1,%2,%3}, {%4,%5,%6,%7}, {%8,%9}, {%0,%1,%2,%3};"
        : "+f"(d[0]), "+f"(d[1]), "+f"(d[2]), "+f"(d[3])
        : "r"(a[0]), "r"(a[1]), "r"(a[2]), "r"(a[3]), "r"(b[0]), "r"(b[1]));
}
#define CP_ASYNC16(dst, src) \
    asm volatile("cp.async.cg.shared.global [%0], [%1], 16;" :: "r"(dst), "l"(src))
#define CP_COMMIT()  asm volatile("cp.async.commit_group;" ::: "memory")
#define CP_WAIT_1()  asm volatile("cp.async.wait_group 1;" ::: "memory")
#define CP_WAIT_0()  asm volatile("cp.async.wait_group 0;" ::: "memory")

// ---------------- prep kernels ----------------
__global__ void conv_hilo(const float* __restrict__ X,
                          __nv_bfloat16* __restrict__ hi, __nv_bfloat16* __restrict__ lo)
{
    const int i = blockIdx.x * blockDim.x + threadIdx.x;   // per float4
    float4 v = ((const float4*)X)[i];
    __nv_bfloat16 hx = __float2bfloat16(v.x), hy = __float2bfloat16(v.y);
    __nv_bfloat16 hz = __float2bfloat16(v.z), hw = __float2bfloat16(v.w);
    __nv_bfloat162* H = (__nv_bfloat162*)hi;
    __nv_bfloat162* L = (__nv_bfloat162*)lo;
    H[i * 2 + 0] = __nv_bfloat162{hx, hy};
    H[i * 2 + 1] = __nv_bfloat162{hz, hw};
    L[i * 2 + 0] = __nv_bfloat162{__float2bfloat16(v.x - __bfloat162float(hx)),
                                  __float2bfloat16(v.y - __bfloat162float(hy))};
    L[i * 2 + 1] = __nv_bfloat162{__float2bfloat16(v.z - __bfloat162float(hz)),
                                  __float2bfloat16(v.w - __bfloat162float(hw))};
}

// W [Kdim x Ndim] fp32 -> WT [Ndim x Kdim] bf16 hi/lo
__global__ void transpose_conv(const float* __restrict__ W,
                               __nv_bfloat16* __restrict__ Thi, __nv_bfloat16* __restrict__ Tlo,
                               int Kdim, int Ndim)
{
    __shared__ float t[32][33];
    const int n0 = blockIdx.x * 32, k0 = blockIdx.y * 32;
    const int tx = threadIdx.x, ty = threadIdx.y;
#pragma unroll
    for (int s = 0; s < 32; s += 8)
        t[ty + s][tx] = W[(k0 + ty + s) * Ndim + n0 + tx];
    __syncthreads();
#pragma unroll
    for (int s = 0; s < 32; s += 8) {
        float v = t[tx][ty + s];
        __nv_bfloat16 h = __float2bfloat16(v);
        Thi[(n0 + ty + s) * Kdim + k0 + tx] = h;
        Tlo[(n0 + ty + s) * Kdim + k0 + tx] = __float2bfloat16(v - __bfloat162float(h));
    }
}

// ---------------- S_v = (sum_t x_t) @ W_v + 4096*b_v ----------------
__global__ void xsum_kernel(const float* __restrict__ x)
{
    const int c  = threadIdx.x;
    const int t0 = blockIdx.x * 128;
    float s = 0.f;
#pragma unroll 4
    for (int t = t0; t < t0 + 128; t++)
        s += x[t * E_DIM + c];
    atomicAdd(&g_xsum[c], s);
}

__global__ void sv_gemv(const float* __restrict__ W_qkv, const float* __restrict__ b_qkv)
{
    __shared__ float xs[E_DIM];
    const int c = threadIdx.x;
    xs[c] = g_xsum[c];
    __syncthreads();
    float s = 4096.f * b_qkv[2 * E_DIM + c];
    for (int e = 0; e < E_DIM; e++)
        s = fmaf(xs[e], W_qkv[e * QKV_LD + 2 * E_DIM + c], s);
    g_sv[c] = s;
}

// ---------------- bf16x3 tensor-core GEMM ----------------
#define KC 32
#define NCH (KDIM / KC)
#define LDSB 80
#define ST_AH 0
#define ST_AL 5120
#define ST_BH 10240
#define ST_BL 20480
#define STAGE_B 30720
#define GEMM_SMEM_BYTES (2 * STAGE_B)

__device__ __forceinline__ void gemm_load_chunk(
    uint32_t stage_sb, const __nv_bfloat16* Ahi, const __nv_bfloat16* Alo,
    const __nv_bfloat16* Bhi, const __nv_bfloat16* Blo,
    int m0, int n0, int kb, int tid)
{
#pragma unroll
    for (int i = 0; i < 2; i++) {
        const int idx = tid + i * 128;
        const int r = idx >> 2, seg = idx & 3;
        const uint32_t so = stage_sb + (uint32_t)(r * LDSB + seg * 16);
        const long ga = (long)(m0 + r) * KDIM + kb + seg * 8;
        CP_ASYNC16(so + ST_AH, Ahi + ga);
        CP_ASYNC16(so + ST_AL, Alo + ga);
    }
#pragma unroll
    for (int i = 0; i < 4; i++) {
        const int idx = tid + i * 128;
        const int r = idx >> 2, seg = idx & 3;
        const uint32_t so = stage_sb + (uint32_t)(r * LDSB + seg * 16);
        const long gb = (long)(n0 + r) * KDIM + kb + seg * 8;
        CP_ASYNC16(so + ST_BH, Bhi + gb);
        CP_ASYNC16(so + ST_BL, Blo + gb);
    }
}

__global__ void __launch_bounds__(128, 3)
gemm_mma(const __nv_bfloat16* __restrict__ Ahi, const __nv_bfloat16* __restrict__ Alo,
         const __nv_bfloat16* __restrict__ Bhi, const __nv_bfloat16* __restrict__ Blo,
         const float* __restrict__ bias, float* __restrict__ C, int ldc, int mode,
         int m_base,
         const float* __restrict__ cema, const float* __restrict__ aw)
{
    extern __shared__ __align__(16) char smem[];
    const uint32_t sb = smem_u32(smem);
    const int tid = threadIdx.x;
    const int wn = tid >> 5, lane = tid & 31;
    const int m0 = m_base + blockIdx.y * 64, n0 = blockIdx.x * 128;

    const uint32_t a_off = (uint32_t)(lane & 15) * LDSB + ((lane >> 4) << 4);
    const uint32_t b_off = (uint32_t)(wn * 32 + (lane & 7)) * LDSB + (((lane >> 3) & 1) << 4);

    float acc[4][4][4];
#pragma unroll
    for (int mt = 0; mt < 4; mt++)
#pragma unroll
        for (int nt = 0; nt < 4; nt++)
#pragma unroll
            for (int c = 0; c < 4; c++) acc[mt][nt][c] = 0.f;

    gemm_load_chunk(sb, Ahi, Alo, Bhi, Blo, m0, n0, 0, tid);
    CP_COMMIT();

    for (int ch = 0; ch < NCH; ch++) {
        const uint32_t st = sb + (uint32_t)((ch & 1) * STAGE_B);
        if (ch + 1 < NCH) {
            gemm_load_chunk(sb + (uint32_t)(((ch + 1) & 1) * STAGE_B),
                            Ahi, Alo, Bhi, Blo, m0, n0, (ch + 1) * KC, tid);
            CP_COMMIT();
            CP_WAIT_1();
        } else {
            CP_WAIT_0();
        }
        __syncthreads();

#pragma unroll
        for (int ks = 0; ks < 2; ks++) {
            const uint32_t kofs = ks * 32;
            uint32_t bh[4][2], bl[4][2];
#pragma unroll
            for (int nt = 0; nt < 4; nt++) {
                ldsm_x2(bh[nt], st + ST_BH + b_off + nt * (8 * LDSB) + kofs);
                ldsm_x2(bl[nt], st + ST_BL + b_off + nt * (8 * LDSB) + kofs);
            }
#pragma unroll
            for (int mt = 0; mt < 4; mt++) {
                uint32_t ah[4], al[4];
                ldsm_x4(ah, st + ST_AH + a_off + mt * (16 * LDSB) + kofs);
                ldsm_x4(al, st + ST_AL + a_off + mt * (16 * LDSB) + kofs);
#pragma unroll
                for (int nt = 0; nt < 4; nt++) {
                    mma_bf16(acc[mt][nt], ah, bh[nt]);
                    mma_bf16(acc[mt][nt], ah, bl[nt]);
                    mma_bf16(acc[mt][nt], al, bh[nt]);
                }
            }
        }
        __syncthreads();
    }

    float w0 = 1.f, w1 = 0.f;
    if (mode == 1) {
        float a0 = aw[0], a1 = aw[1];
        float mx = fmaxf(a0, a1);
        float e0 = expf(a0 - mx), e1 = expf(a1 - mx);
        float inv = 1.f / (e0 + e1);
        w0 = e0 * inv; w1 = e1 * inv;
    }

#pragma unroll
    for (int mt = 0; mt < 4; mt++) {
        const int r0 = m0 + mt * 16 + (lane >> 2);
#pragma unroll
        for (int nt = 0; nt < 4; nt++) {
            const int col = n0 + wn * 32 + nt * 8 + (lane & 3) * 2;
            const float b0v = bias[col], b1v = bias[col + 1];
            float2 v0 = make_float2(acc[mt][nt][0] + b0v, acc[mt][nt][1] + b1v);
            float2 v1 = make_float2(acc[mt][nt][2] + b0v, acc[mt][nt][3] + b1v);
            if (mode == 1) {
                float2 c0 = *(const float2*)&cema[r0 * ldc + col];
                float2 c1 = *(const float2*)&cema[(r0 + 8) * ldc + col];
                v0.x = fmaf(w0, v0.x, w1 * c0.x);  v0.y = fmaf(w0, v0.y, w1 * c0.y);
                v1.x = fmaf(w0, v1.x, w1 * c1.x);  v1.y = fmaf(w0, v1.y, w1 * c1.y);
            }
            *(float2*)&C[r0 * ldc + col]       = v0;
            *(float2*)&C[(r0 + 8) * ldc + col] = v1;
        }
    }
}

// ---------------- fused block-local attention (half-range) ----------------
#define ATTN_SMEM_FLOATS (16384 + 8192 + 128)

__global__ void __launch_bounds__(256)
attn_kernel(int blk_base)
{
    extern __shared__ float sm[];
    float* qv     = sm;
    float* ks     = sm + 8192;
    float* Est    = sm;
    float* vv     = sm + 16384;
    float* rowinv = sm + 16384 + 8192;

    const int tid = threadIdx.x;
    const int h   = blockIdx.x >> 4;            // grid = NH * 16
    const int blk = blk_base + (blockIdx.x & 15);
    const int t0  = blk * WSZ;
    const int coff = h * DK;

    for (int idx = tid; idx < 2048; idx += 256) {
        const int i = idx >> 4, d4 = (idx & 15) << 2;
        const float* src = &g_qkv[(t0 + i) * QKV_LD + coff + d4];
        float4 q4 = *(const float4*)src;
        float4 k4 = *(const float4*)(src + E_DIM);
        float4 v4 = *(const float4*)(src + 2 * E_DIM);
        qv[(d4 + 0) * 128 + i] = q4.x;  ks[(d4 + 0) * 128 + i] = k4.x;
        qv[(d4 + 1) * 128 + i] = q4.y;  ks[(d4 + 1) * 128 + i] = k4.y;
        qv[(d4 + 2) * 128 + i] = q4.z;  ks[(d4 + 2) * 128 + i] = k4.z;
        qv[(d4 + 3) * 128 + i] = q4.w;  ks[(d4 + 3) * 128 + i] = k4.w;
        *(float4*)&vv[i * 64 + d4] = v4;
    }
    __syncthreads();

    const int tx = tid & 15, ty = tid >> 4;
    const int ib = tx * 8, jb = ty * 8;
    float accS[8][8];
#pragma unroll
    for (int r = 0; r < 8; r++)
#pragma unroll
        for (int c = 0; c < 8; c++) accS[r][c] = 0.f;

#pragma unroll 4
    for (int d = 0; d < 64; d++) {
        float qr[8], kr[8];
        *(float4*)&qr[0] = *(const float4*)&qv[d * 128 + ib];
        *(float4*)&qr[4] = *(const float4*)&qv[d * 128 + ib + 4];
        *(float4*)&kr[0] = *(const float4*)&ks[d * 128 + jb];
        *(float4*)&kr[4] = *(const float4*)&ks[d * 128 + jb + 4];
#pragma unroll
        for (int r = 0; r < 8; r++)
#pragma unroll
            for (int c = 0; c < 8; c++)
                accS[r][c] = fmaf(qr[r], kr[c], accS[r][c]);
    }
    __syncthreads();

#pragma unroll
    for (int c = 0; c < 8; c++) {
        const int j = jb + c;
        float e[8];
#pragma unroll
        for (int r = 0; r < 8; r++) {
            const int i = ib + r;
            e[r] = (j <= i) ? (expf(accS[r][c] * 0.125f) - 1.0f) : 0.0f;
        }
        *(float4*)&Est[j * 128 + ib]     = make_float4(e[0], e[1], e[2], e[3]);
        *(float4*)&Est[j * 128 + ib + 4] = make_float4(e[4], e[5], e[6], e[7]);
    }
    __syncthreads();

    if (tid < 128) {
        float s = 0.f;
#pragma unroll 4
        for (int j = 0; j < 128; j++) s += Est[j * 128 + tid];
        rowinv[tid] = 1.0f / (s + 4096.0f);
    }
    __syncthreads();

    const int i0 = ty * 8, d0 = tx * 4;
    float accO[8][4];
#pragma unroll
    for (int r = 0; r < 8; r++)
#pragma unroll
        for (int c = 0; c < 4; c++) accO[r][c] = 0.f;

#pragma unroll 2
    for (int j = 0; j < 128; j++) {
        float er[8];
        *(float4*)&er[0] = *(const float4*)&Est[j * 128 + i0];
        *(float4*)&er[4] = *(const float4*)&Est[j * 128 + i0 + 4];
        float4 v4 = *(const float4*)&vv[j * 64 + d0];
#pragma unroll
        for (int r = 0; r < 8; r++) {
            accO[r][0] = fmaf(er[r], v4.x, accO[r][0]);
            accO[r][1] = fmaf(er[r], v4.y, accO[r][1]);
            accO[r][2] = fmaf(er[r], v4.z, accO[r][2]);
            accO[r][3] = fmaf(er[r], v4.w, accO[r][3]);
        }
    }

    const float4 sv4 = *(const float4*)&g_sv[coff + d0];
#pragma unroll
    for (int r = 0; r < 8; r++) {
        const int i = i0 + r;
        const float riv = rowinv[i];
        float4 o;
        o.x = (accO[r][0] + sv4.x) * riv;
        o.y = (accO[r][1] + sv4.y) * riv;
        o.z = (accO[r][2] + sv4.z) * riv;
        o.w = (accO[r][3] + sv4.w) * riv;
        __nv_bfloat16 hx = __float2bfloat16(o.x), hy = __float2bfloat16(o.y);
        __nv_bfloat16 hz = __float2bfloat16(o.z), hw = __float2bfloat16(o.w);
        const int base = ((t0 + i) * E_DIM + coff + d0) >> 1;
        __nv_bfloat162* H = (__nv_bfloat162*)g_ahi;
        __nv_bfloat162* L = (__nv_bfloat162*)g_alo;
        H[base + 0] = __nv_bfloat162{hx, hy};
        H[base + 1] = __nv_bfloat162{hz, hw};
        L[base + 0] = __nv_bfloat162{__float2bfloat16(o.x - __bfloat162float(hx)),
                                     __float2bfloat16(o.y - __bfloat162float(hy))};
        L[base + 1] = __nv_bfloat162{__float2bfloat16(o.z - __bfloat162float(hz)),
                                     __float2bfloat16(o.w - __bfloat162float(hw))};
    }
}

// ---------------- CEMA: chunked linear scan ----------------
__global__ void __launch_bounds__(128)
cema_pass1(const float* __restrict__ x, const float* __restrict__ p_coeff,
           const float* __restrict__ q_coeff, const float* __restrict__ gamma)
{
    const int gid  = blockIdx.x * 128 + threadIdx.x;
    const int e    = gid & 511;
    const int chnk = gid >> 9;
    float p[NDIMS], q[NDIMS], g[NDIMS], h[NDIMS];
#pragma unroll
    for (int d = 0; d < NDIMS; d++) {
        p[d] = p_coeff[e * NDIMS + d];
        q[d] = q_coeff[e * NDIMS + d];
        g[d] = gamma  [e * NDIMS + d];
        h[d] = 0.f;
    }
    const int tbase = chnk * CLEN;
    for (int t = 0; t < CLEN; t++) {
        const float xv = x[(tbase + t) * E_DIM + e];
        float y = 0.f;
#pragma unroll
        for (int d = 0; d < NDIMS; d++) {
            h[d] = fmaf(q[d], h[d], p[d] * xv);
            y    = fmaf(g[d], h[d], y);
        }
        g_cema[(tbase + t) * E_DIM + e] = y;
    }
#pragma unroll
    for (int d = 0; d < NDIMS; d++)
        g_hend[chnk * (E_DIM * NDIMS) + e * NDIMS + d] = h[d];
}

__global__ void __launch_bounds__(128)
cema_carry(const float* __restrict__ q_coeff)
{
    const int gid = blockIdx.x * 128 + threadIdx.x;
    const float q = q_coeff[gid];
    float qc = q;
#pragma unroll
    for (int i = 0; i < 6; i++) qc *= qc;              // q^64
    float G = 0.f;
    for (int cb = 0; cb < CHUNKS; cb += 16) {
        float v[16];
#pragma unroll
        for (int i = 0; i < 16; i++)
            v[i] = g_hend[(cb + i) * (E_DIM * NDIMS) + gid];
#pragma unroll
        for (int i = 0; i < 16; i++) {
            g_carry[(cb + i) * (E_DIM * NDIMS) + gid] = G;
            G = fmaf(qc, G, v[i]);
        }
    }
}

__global__ void __launch_bounds__(128)
cema_pass2(const float* __restrict__ q_coeff, const float* __restrict__ gamma)
{
    const int gid  = blockIdx.x * 128 + threadIdx.x;
    const int e    = gid & 511;
    const int chnk = gid >> 9;
    if (chnk == 0) return;
    float q[NDIMS], w[NDIMS];
#pragma unroll
    for (int d = 0; d < NDIMS; d++) {
        q[d] = q_coeff[e * NDIMS + d];
        w[d] = gamma[e * NDIMS + d] * g_carry[chnk * (E_DIM * NDIMS) + e * NDIMS + d];
    }
    const int tbase = chnk * CLEN;
    for (int t = 0; t < CLEN; t++) {
        float y = 0.f;
#pragma unroll
        for (int d = 0; d < NDIMS; d++) {
            w[d] *= q[d];
            y    += w[d];
        }
        g_cema[(tbase + t) * E_DIM + e] += y;
    }
}

// ---------------------------- launch ----------------------------
extern "C" void kernel_launch(void* const* d_in, const int* in_sizes, int n_in,
                              void* d_out, int out_size)
{
    (void)in_sizes; (void)n_in; (void)out_size;
    const float* x       = (const float*)d_in[0];
    const float* W_qkv   = (const float*)d_in[1];
    const float* b_qkv   = (const float*)d_in[2];
    const float* W_out   = (const float*)d_in[3];
    const float* b_out   = (const float*)d_in[4];
    const float* p_coeff = (const float*)d_in[6];
    const float* q_coeff = (const float*)d_in[7];
    const float* gamma   = (const float*)d_in[8];
    const float* aw      = (const float*)d_in[9];
    float* out = (float*)d_out;

    float *qkvp, *cemap, *xsump;
    __nv_bfloat16 *xhi, *xlo, *ahi, *alo, *wqh, *wql, *woh, *wol;
    cudaGetSymbolAddress((void**)&qkvp,  g_qkv);
    cudaGetSymbolAddress((void**)&cemap, g_cema);
    cudaGetSymbolAddress((void**)&xsump, g_xsum);
    cudaGetSymbolAddress((void**)&xhi, g_xhi);
    cudaGetSymbolAddress((void**)&xlo, g_xlo);
    cudaGetSymbolAddress((void**)&ahi, g_ahi);
    cudaGetSymbolAddress((void**)&alo, g_alo);
    cudaGetSymbolAddress((void**)&wqh, g_wqT_hi);
    cudaGetSymbolAddress((void**)&wql, g_wqT_lo);
    cudaGetSymbolAddress((void**)&woh, g_woT_hi);
    cudaGetSymbolAddress((void**)&wol, g_woT_lo);

    cudaFuncSetAttribute(gemm_mma, cudaFuncAttributeMaxDynamicSharedMemorySize, GEMM_SMEM_BYTES);
    cudaFuncSetAttribute(attn_kernel, cudaFuncAttributeMaxDynamicSharedMemorySize,
                         ATTN_SMEM_FLOATS * (int)sizeof(float));

    // one-time host-object setup — SAME topology as R12 (2 extra streams), which
    // passed the memory guard. No priority streams.
    static cudaStream_t s_side = nullptr, s_attn = nullptr;
    static cudaEvent_t  e_fork = nullptr, e_sv = nullptr, e_conv = nullptr,
                        e_g1a = nullptr, e_attnB = nullptr, e_side = nullptr;
    if (s_side == nullptr) {
        cudaStreamCreateWithFlags(&s_side, cudaStreamNonBlocking);
        cudaStreamCreateWithFlags(&s_attn, cudaStreamNonBlocking);
        cudaEventCreateWithFlags(&e_fork,  cudaEventDisableTiming);
        cudaEventCreateWithFlags(&e_sv,    cudaEventDisableTiming);
        cudaEventCreateWithFlags(&e_conv,  cudaEventDisableTiming);
        cudaEventCreateWithFlags(&e_g1a,   cudaEventDisableTiming);
        cudaEventCreateWithFlags(&e_attnB, cudaEventDisableTiming);
        cudaEventCreateWithFlags(&e_side,  cudaEventDisableTiming);
    }

    // ---- fork
    cudaEventRecord(e_fork, 0);
    cudaStreamWaitEvent(s_side, e_fork, 0);
    cudaStreamWaitEvent(s_attn, e_fork, 0);

    // side stream: S_v, CEMA chain, W_out transpose
    cudaMemsetAsync(xsump, 0, E_DIM * sizeof(float), s_side);
    xsum_kernel<<<NBLK, E_DIM, 0, s_side>>>(x);
    sv_gemv<<<1, E_DIM, 0, s_side>>>(W_qkv, b_qkv);
    cudaEventRecord(e_sv, s_side);
    cema_pass1<<<(E_DIM * CHUNKS) / 128, 128, 0, s_side>>>(x, p_coeff, q_coeff, gamma);
    cema_carry<<<(E_DIM * NDIMS) / 128, 128, 0, s_side>>>(q_coeff);
    cema_pass2<<<(E_DIM * CHUNKS) / 128, 128, 0, s_side>>>(q_coeff, gamma);
    transpose_conv<<<dim3(E_DIM / 32, E_DIM / 32), dim3(32, 8), 0, s_side>>>(
        W_out, woh, wol, E_DIM, E_DIM);
    cudaEventRecord(e_side, s_side);

    // attn stream: W_qkv transpose (concurrent with conv_hilo on main)
    transpose_conv<<<dim3(QKV_LD / 32, E_DIM / 32), dim3(32, 8), 0, s_attn>>>(
        W_qkv, wqh, wql, E_DIM, QKV_LD);
    // (e_wq implied: gemm1b is on the same stream; gemm1a on main waits e_conv
    //  which is recorded after conv_hilo; main also needs W_qkv -> record event)
    cudaEventRecord(e_attnB, s_attn);   // reuse as "wq done" marker for main

    // main: x hi/lo conversion
    conv_hilo<<<(N_TOK * E_DIM / 4) / 256, 256>>>(x, xhi, xlo);
    cudaEventRecord(e_conv, 0);

    // gemm1 half A on MAIN (launched first -> CTAs dispatched first)
    cudaStreamWaitEvent(0, e_attnB, 0);  // wait W_qkv transpose
    gemm_mma<<<dim3(QKV_LD / 128, (N_TOK / 2) / 64), 128, GEMM_SMEM_BYTES>>>(
        xhi, xlo, wqh, wql, b_qkv, qkvp, QKV_LD, 0, 0, nullptr, nullptr);
    cudaEventRecord(e_g1a, 0);

    // gemm1 half B on s_attn, CONCURRENT with half A (waits conv only; W_qkv
    // transpose is earlier on this same stream)
    cudaStreamWaitEvent(s_attn, e_conv, 0);
    gemm_mma<<<dim3(QKV_LD / 128, (N_TOK / 2) / 64), 128, GEMM_SMEM_BYTES, s_attn>>>(
        xhi, xlo, wqh, wql, b_qkv, qkvp, QKV_LD, 0, N_TOK / 2, nullptr, nullptr);

    // attn half B on s_attn (after gemm1b, same stream; needs S_v)
    cudaStreamWaitEvent(s_attn, e_sv, 0);
    attn_kernel<<<NH * 16, 256, ATTN_SMEM_FLOATS * (int)sizeof(float), s_attn>>>(16);
    cudaEventRecord(e_attnB, s_attn);

    // attn half A on main (after gemm1a, same stream; needs S_v)
    cudaStreamWaitEvent(0, e_sv, 0);
    attn_kernel<<<NH * 16, 256, ATTN_SMEM_FLOATS * (int)sizeof(float)>>>(0);

    // join, then fused output GEMM on main
    cudaStreamWaitEvent(0, e_attnB, 0);
    cudaStreamWaitEvent(0, e_side, 0);
    gemm_mma<<<dim3(E_DIM / 128, N_TOK / 64), 128, GEMM_SMEM_BYTES>>>(
        ahi, alo, woh, wol, b_out, out, E_DIM, 1, 0, cemap, aw);
}